// round 1
// baseline (speedup 1.0000x reference)
#include <cuda_runtime.h>
#include <cuda_bf16.h>
#include <math.h>

// Problem dims
#define BB 16
#define TT 512
#define II 256
#define HH 512
#define MM 2048
#define DD 64
#define NHD 4
#define OO 256
#define G4H 2048  // 4*H
#define EPSV 1e-8f

#define NBLK 128  // persistent LSTM grid (<= 148 SMs -> co-resident)

// ---------------- scratch (static device globals; no runtime alloc) ------------
__device__ float g_pregates[(size_t)BB * TT * G4H];   // 64 MB, row r = b*T+t
__device__ float g_part[16 * BB * G4H];               // 2 MB split-K partials
__device__ float g_h[BB * HH];
__device__ float g_c[BB * HH];
__device__ float g_combined[(size_t)BB * TT * (HH + NHD * DD)];  // 24 MB, [8192][768]
__device__ float g_keys[(size_t)BB * TT * NHD * DD];  // [32768][64]
__device__ float g_sims[(size_t)BB * TT * NHD * MM];  // 256 MB, [32768][2048]
__device__ float g_reads[(size_t)BB * TT * NHD * DD]; // [32768][64]
__device__ float g_WhhT[HH * G4H];                    // [512][2048]
__device__ float g_memnorm[MM];
__device__ unsigned g_bar_count;
__device__ unsigned g_bar_phase;

// ---------------- helpers ----------------
__device__ __forceinline__ float sigmoidf_(float x) {
    return 1.0f / (1.0f + __expf(-x));
}

// Self-resetting grid barrier (phase generation counter; safe across graph replays).
__device__ __forceinline__ void grid_bar(unsigned& target) {
    __syncthreads();
    if (threadIdx.x == 0) {
        __threadfence();
        if (atomicAdd(&g_bar_count, 1) == NBLK - 1) {
            g_bar_count = 0;
            __threadfence();
            atomicAdd(&g_bar_phase, 1);
        } else {
            while (*((volatile unsigned*)&g_bar_phase) != target) { __nanosleep(64); }
            __threadfence();
        }
        target += 1;
    }
    __syncthreads();
}

// ---------------- small prep kernels ----------------
__global__ void transpose_whh_kernel(const float* __restrict__ W_hh) {
    int idx = blockIdx.x * 256 + threadIdx.x;  // total 2048*512
    int g = idx & (G4H - 1);
    int k = idx >> 11;
    g_WhhT[k * G4H + g] = W_hh[g * HH + k];
}

__global__ void memnorm_kernel(const float* __restrict__ memory) {
    __shared__ float s[64];
    int m = blockIdx.x;
    float v = memory[m * DD + threadIdx.x];
    s[threadIdx.x] = v * v;
    __syncthreads();
    for (int o = 32; o > 0; o >>= 1) {
        if (threadIdx.x < o) s[threadIdx.x] += s[threadIdx.x + o];
        __syncthreads();
    }
    if (threadIdx.x == 0) g_memnorm[m] = sqrtf(s[0]);
}

// ---------------- generic fp32 SGEMM ----------------
// C[m][n] = sum_k A[m*lda+k] * (BT ? B[n*ldb+k] : B[k*ldb+n]) + bias1[n] + bias2[n]
// Requires M%64==0, N%64==0, K%16==0, lda/ldb %4==0.
template <bool BT>
__global__ void __launch_bounds__(256) sgemm_kernel(
    const float* __restrict__ A, const float* __restrict__ B, float* __restrict__ C,
    int M, int N, int K, int lda, int ldb, int ldc,
    const float* __restrict__ bias1, const float* __restrict__ bias2)
{
    __shared__ float As[16][64];
    __shared__ float Bs[16][64];
    int tid = threadIdx.x;
    int m0 = blockIdx.y * 64;
    int n0 = blockIdx.x * 64;
    int tx = tid & 15, ty = tid >> 4;

    float acc[4][4];
#pragma unroll
    for (int i = 0; i < 4; i++)
#pragma unroll
        for (int j = 0; j < 4; j++) acc[i][j] = 0.0f;

    int la_m = tid >> 2;           // 0..63
    int la_k = (tid & 3) * 4;      // 0,4,8,12

    for (int k0 = 0; k0 < K; k0 += 16) {
        float4 a4 = *(const float4*)(A + (size_t)(m0 + la_m) * lda + k0 + la_k);
        As[la_k + 0][la_m] = a4.x;
        As[la_k + 1][la_m] = a4.y;
        As[la_k + 2][la_m] = a4.z;
        As[la_k + 3][la_m] = a4.w;
        if (BT) {
            float4 b4 = *(const float4*)(B + (size_t)(n0 + la_m) * ldb + k0 + la_k);
            Bs[la_k + 0][la_m] = b4.x;
            Bs[la_k + 1][la_m] = b4.y;
            Bs[la_k + 2][la_m] = b4.z;
            Bs[la_k + 3][la_m] = b4.w;
        } else {
            int lb_k = tid >> 4;            // 0..15
            int lb_n = (tid & 15) * 4;      // 0..60
            float4 b4 = *(const float4*)(B + (size_t)(k0 + lb_k) * ldb + n0 + lb_n);
            *(float4*)&Bs[lb_k][lb_n] = b4;
        }
        __syncthreads();
#pragma unroll
        for (int kk = 0; kk < 16; kk++) {
            float4 av = *(const float4*)&As[kk][ty * 4];
            float4 bv = *(const float4*)&Bs[kk][tx * 4];
            float ar[4] = {av.x, av.y, av.z, av.w};
            float br[4] = {bv.x, bv.y, bv.z, bv.w};
#pragma unroll
            for (int i = 0; i < 4; i++)
#pragma unroll
                for (int j = 0; j < 4; j++) acc[i][j] += ar[i] * br[j];
        }
        __syncthreads();
    }

#pragma unroll
    for (int i = 0; i < 4; i++) {
        int m = m0 + ty * 4 + i;
#pragma unroll
        for (int j = 0; j < 4; j++) {
            int n = n0 + tx * 4 + j;
            float v = acc[i][j];
            if (bias1) v += bias1[n];
            if (bias2) v += bias2[n];
            C[(size_t)m * ldc + n] = v;
        }
    }
}

// ---------------- persistent LSTM kernel ----------------
__global__ void __launch_bounds__(256) lstm_kernel() {
    int tid = threadIdx.x;
    int gid = blockIdx.x * 256 + tid;

    // zero initial state
    if (gid < BB * HH) { g_h[gid] = 0.0f; g_c[gid] = 0.0f; }

    unsigned target = 0;
    if (tid == 0) target = *((volatile unsigned*)&g_bar_phase) + 1;
    grid_bar(target);

    __shared__ float h_sm[BB][32];
    int ksplit = blockIdx.x >> 3;               // 0..15, 32 k each
    int gcol = (blockIdx.x & 7) * 256 + tid;    // 0..2047

    for (int t = 0; t < TT; t++) {
        // stage this block's h chunk [16][32]
        for (int e = tid; e < BB * 32; e += 256) {
            int b = e >> 5, kk = e & 31;
            h_sm[b][kk] = g_h[b * HH + ksplit * 32 + kk];
        }
        __syncthreads();

        // phase 1: partial gates for all 16 batches, one gate column per thread
        float acc[BB];
#pragma unroll
        for (int b = 0; b < BB; b++) acc[b] = 0.0f;
#pragma unroll
        for (int kq = 0; kq < 8; kq++) {
            float w0 = g_WhhT[(ksplit * 32 + kq * 4 + 0) * G4H + gcol];
            float w1 = g_WhhT[(ksplit * 32 + kq * 4 + 1) * G4H + gcol];
            float w2 = g_WhhT[(ksplit * 32 + kq * 4 + 2) * G4H + gcol];
            float w3 = g_WhhT[(ksplit * 32 + kq * 4 + 3) * G4H + gcol];
#pragma unroll
            for (int b = 0; b < BB; b++) {
                float4 h4 = *(const float4*)&h_sm[b][kq * 4];
                acc[b] += h4.x * w0 + h4.y * w1 + h4.z * w2 + h4.w * w3;
            }
        }
#pragma unroll
        for (int b = 0; b < BB; b++)
            g_part[(ksplit * BB + b) * G4H + gcol] = acc[b];

        grid_bar(target);

        // phase 2: reduce partials + activations + state update (first 8192 threads)
        if (gid < BB * HH) {
            int b = gid >> 9, j = gid & (HH - 1);
            size_t base = ((size_t)(b * TT + t)) * G4H;
            float gv[4];
#pragma unroll
            for (int q = 0; q < 4; q++) {
                int col = q * HH + j;
                float s = g_pregates[base + col];
#pragma unroll
                for (int ks = 0; ks < 16; ks++)
                    s += g_part[(ks * BB + b) * G4H + col];
                gv[q] = s;
            }
            float cold = g_c[gid];
            float ig = sigmoidf_(gv[0]);
            float fg = sigmoidf_(gv[1]);
            float gg = tanhf(gv[2]);
            float og = sigmoidf_(gv[3]);
            float cn = fg * cold + ig * gg;
            float hn = og * tanhf(cn);
            g_c[gid] = cn;
            g_h[gid] = hn;
            g_combined[((size_t)(b * TT + t)) * 768 + j] = hn;
        }

        grid_bar(target);
    }
}

// ---------------- softmax over memory slots (with cosine scaling) --------------
__global__ void __launch_bounds__(256) softmax_kernel() {
    __shared__ float red[256];
    __shared__ float s_kn;
    int p = blockIdx.x;          // 0..32767 (= (b*T+t)*4 + n)
    int tid = threadIdx.x;

    // key norm
    float kv = 0.0f;
    if (tid < DD) {
        float k = g_keys[(size_t)p * DD + tid];
        kv = k * k;
    }
    red[tid] = kv;
    __syncthreads();
    for (int o = 128; o > 0; o >>= 1) {
        if (tid < o) red[tid] += red[tid + o];
        __syncthreads();
    }
    if (tid == 0) s_kn = sqrtf(red[0]);
    __syncthreads();
    float kn = s_kn;
    __syncthreads();

    float v[8];
    float mx = -3.0e38f;
#pragma unroll
    for (int i = 0; i < 8; i++) {
        int m = tid + i * 256;
        float s = g_sims[(size_t)p * MM + m];
        s = s / fmaxf(kn * g_memnorm[m], EPSV);
        v[i] = s;
        mx = fmaxf(mx, s);
    }
    red[tid] = mx;
    __syncthreads();
    for (int o = 128; o > 0; o >>= 1) {
        if (tid < o) red[tid] = fmaxf(red[tid], red[tid + o]);
        __syncthreads();
    }
    mx = red[0];
    __syncthreads();

    float sum = 0.0f;
#pragma unroll
    for (int i = 0; i < 8; i++) {
        v[i] = __expf(v[i] - mx);
        sum += v[i];
    }
    red[tid] = sum;
    __syncthreads();
    for (int o = 128; o > 0; o >>= 1) {
        if (tid < o) red[tid] += red[tid + o];
        __syncthreads();
    }
    float inv = 1.0f / red[0];
#pragma unroll
    for (int i = 0; i < 8; i++) {
        int m = tid + i * 256;
        g_sims[(size_t)p * MM + m] = v[i] * inv;
    }
}

// reads [32768][64] -> combined[r][512 + n*64 + d]
__global__ void copy_reads_kernel() {
    int idx = blockIdx.x * 256 + threadIdx.x;   // 0 .. 32768*64-1
    int p = idx >> 6;
    int d = idx & 63;
    int r = p >> 2;
    int n = p & 3;
    g_combined[(size_t)r * 768 + HH + n * DD + d] = g_reads[idx];
}

// ---------------- launch ----------------
extern "C" void kernel_launch(void* const* d_in, const int* in_sizes, int n_in,
                              void* d_out, int out_size) {
    const float* x      = (const float*)d_in[0];
    const float* memory = (const float*)d_in[1];
    const float* W_ih   = (const float*)d_in[2];
    const float* W_hh   = (const float*)d_in[3];
    const float* b_ih   = (const float*)d_in[4];
    const float* b_hh   = (const float*)d_in[5];
    const float* W_if   = (const float*)d_in[6];
    const float* b_if   = (const float*)d_in[7];
    const float* W_out  = (const float*)d_in[8];
    const float* b_out  = (const float*)d_in[9];
    float* out = (float*)d_out;

    float *pg, *comb, *keys, *sims, *reads;
    cudaGetSymbolAddress((void**)&pg, g_pregates);
    cudaGetSymbolAddress((void**)&comb, g_combined);
    cudaGetSymbolAddress((void**)&keys, g_keys);
    cudaGetSymbolAddress((void**)&sims, g_sims);
    cudaGetSymbolAddress((void**)&reads, g_reads);

    // prep
    transpose_whh_kernel<<<(G4H * HH) / 256, 256>>>(W_hh);
    memnorm_kernel<<<MM, 64>>>(memory);

    // pre-gates: [8192,2048] = x[8192,256] @ W_ih^T + (b_ih + b_hh)
    sgemm_kernel<true><<<dim3(G4H / 64, (BB * TT) / 64), 256>>>(
        x, W_ih, pg, BB * TT, G4H, II, II, II, G4H, b_ih, b_hh);

    // sequential LSTM recurrence (persistent, grid-synced)
    lstm_kernel<<<NBLK, 256>>>();

    // keys: [8192,256] = hs(combined[:, :512], lda=768) @ W_if[:256]^T + b_if[:256]
    sgemm_kernel<true><<<dim3(256 / 64, (BB * TT) / 64), 256>>>(
        comb, W_if, keys, BB * TT, NHD * DD, HH, 768, HH, NHD * DD, b_if, nullptr);

    // sims: [32768,2048] = keys[32768,64] @ memory^T
    sgemm_kernel<true><<<dim3(MM / 64, (BB * TT * NHD) / 64), 256>>>(
        keys, memory, sims, BB * TT * NHD, MM, DD, DD, DD, MM, nullptr, nullptr);

    // cosine-scale + softmax (in place on sims)
    softmax_kernel<<<BB * TT * NHD, 256>>>();

    // reads: [32768,64] = attn[32768,2048] @ memory[2048,64]   (NN)
    sgemm_kernel<false><<<dim3(DD / 64, (BB * TT * NHD) / 64), 256>>>(
        sims, memory, reads, BB * TT * NHD, DD, MM, MM, DD, DD, nullptr, nullptr);

    copy_reads_kernel<<<(BB * TT * NHD * DD) / 256, 256>>>();

    // out: [8192,256] = combined[8192,768] @ W_out^T + b_out
    sgemm_kernel<true><<<dim3(OO / 64, (BB * TT) / 64), 256>>>(
        comb, W_out, out, BB * TT, OO, HH + NHD * DD, 768, 768, OO, b_out, nullptr);
}

// round 5
// speedup vs baseline: 1.6644x; 1.6644x over previous
#include <cuda_runtime.h>
#include <cuda_bf16.h>
#include <math.h>

// Problem dims
#define BB 16
#define TT 512
#define II 256
#define HH 512
#define MM 2048
#define DD 64
#define NHD 4
#define OO 256
#define G4H 2048  // 4*H
#define EPSV 1e-8f

#define NBLK 128  // persistent LSTM grid (<= SM count -> co-resident)

// LSTM dynamic smem layout
#define HS2_BYTES  (HH * 8 * 8)        // 32768: h[k][b] as ull pairs
#define PART_BYTES (16 * 258 * 4)      // 16512: partials, padded stride
#define GSM_BYTES  (16 * 17 * 4)       // 1088
#define LSTM_SMEM  (HS2_BYTES + PART_BYTES + GSM_BYTES)  // 50368

typedef unsigned long long ull;

// ---------------- scratch (static device globals; no runtime alloc) ------------
__device__ float g_pregates[(size_t)BB * TT * G4H];   // 64 MB, row r = b*T+t
__device__ float g_hbuf[2][HH * BB];                  // [buf][k*16+b], double buffered
__device__ float g_combined[(size_t)BB * TT * (HH + NHD * DD)];  // [8192][768]
__device__ float g_keys[(size_t)BB * TT * NHD * DD];  // [32768][64]
__device__ float g_sims[(size_t)BB * TT * NHD * MM];  // 256 MB, [32768][2048]
__device__ float g_reads[(size_t)BB * TT * NHD * DD]; // [32768][64]
__device__ float g_WhhT[HH * G4H];                    // [512][2048]
__device__ float g_memnorm[MM];
__device__ unsigned g_bar_count;
__device__ unsigned g_bar_phase;

// ---------------- helpers ----------------
__device__ __forceinline__ float sigmoidf_(float x) {
    return 1.0f / (1.0f + __expf(-x));
}

__device__ __forceinline__ ull packf2(float a, float b) {
    ull r;
    asm("mov.b64 %0, {%1, %2};" : "=l"(r) : "f"(a), "f"(b));
    return r;
}
__device__ __forceinline__ void fma2(ull& d, ull a, ull b) {
    asm("fma.rn.f32x2 %0, %1, %2, %0;" : "+l"(d) : "l"(a), "l"(b));
}

// Self-resetting grid barrier (phase generation counter; safe across graph replays).
__device__ __forceinline__ void grid_bar(unsigned& target) {
    __syncthreads();
    if (threadIdx.x == 0) {
        __threadfence();
        if (atomicAdd(&g_bar_count, 1) == NBLK - 1) {
            g_bar_count = 0;
            __threadfence();
            atomicAdd(&g_bar_phase, 1);
        } else {
            while (*((volatile unsigned*)&g_bar_phase) != target) { __nanosleep(32); }
            __threadfence();
        }
        target += 1;
    }
    __syncthreads();
}

// ---------------- small prep kernels ----------------
__global__ void transpose_whh_kernel(const float* __restrict__ W_hh) {
    int idx = blockIdx.x * 256 + threadIdx.x;  // total 2048*512
    int g = idx & (G4H - 1);
    int k = idx >> 11;
    g_WhhT[k * G4H + g] = W_hh[g * HH + k];
}

__global__ void memnorm_kernel(const float* __restrict__ memory) {
    __shared__ float s[64];
    int m = blockIdx.x;
    float v = memory[m * DD + threadIdx.x];
    s[threadIdx.x] = v * v;
    __syncthreads();
    for (int o = 32; o > 0; o >>= 1) {
        if (threadIdx.x < o) s[threadIdx.x] += s[threadIdx.x + o];
        __syncthreads();
    }
    if (threadIdx.x == 0) g_memnorm[m] = sqrtf(s[0]);
}

// ---------------- fp32 SGEMM, 128xBN tile, 8x(BN/16) microtile, double buffered ----
// C[m][n] = sum_k A[m*lda+k] * (BT ? B[n*ldb+k] : B[k*ldb+n]) + bias1[n] + bias2[n]
// M%128==0, N%BN==0, K%8==0.
template <bool BT, int BN>
__global__ void __launch_bounds__(256) sgemm2(
    const float* __restrict__ A, const float* __restrict__ B, float* __restrict__ C,
    int M, int N, int K, int lda, int ldb, int ldc,
    const float* __restrict__ bias1, const float* __restrict__ bias2)
{
    constexpr int TN = BN / 16;
    __shared__ float As[2][8][132];
    __shared__ float Bs[2][8][BN + 4];

    int tid = threadIdx.x;
    int m0 = blockIdx.y * 128;
    int n0 = blockIdx.x * BN;
    int tx = tid & 15, ty = tid >> 4;

    float acc[8][TN];
#pragma unroll
    for (int i = 0; i < 8; i++)
#pragma unroll
        for (int j = 0; j < TN; j++) acc[i][j] = 0.0f;

    // A loader coords: 128x8 tile, 1 float4/thread
    int a_r = tid >> 1;
    int a_k = (tid & 1) * 4;
    const float* Aptr = A + (size_t)(m0 + a_r) * lda + a_k;

    // B loader coords
    int b_r = 0, b_k = 0, b_n = 0;
    const float* Bptr;
    bool b_act;
    if (BT) {
        b_act = (BN == 128) || (tid < 128);
        b_r = tid >> 1;          // row in [0,BN)
        b_k = (tid & 1) * 4;
        Bptr = B + (size_t)(n0 + b_r) * ldb + b_k;
    } else {
        if (BN == 128) {
            b_act = true;
            b_k = tid >> 5; b_n = (tid & 31) * 4;
        } else {
            b_act = (tid < 128);
            b_k = tid >> 4; b_n = (tid & 15) * 4;
        }
        Bptr = B + (size_t)b_k * ldb + n0 + b_n;
    }

    int KT = K >> 3;

    // prologue: load tile 0
    {
        float4 a4 = *(const float4*)Aptr;
        As[0][a_k + 0][a_r] = a4.x;
        As[0][a_k + 1][a_r] = a4.y;
        As[0][a_k + 2][a_r] = a4.z;
        As[0][a_k + 3][a_r] = a4.w;
        if (b_act) {
            float4 b4 = *(const float4*)Bptr;
            if (BT) {
                Bs[0][b_k + 0][b_r] = b4.x;
                Bs[0][b_k + 1][b_r] = b4.y;
                Bs[0][b_k + 2][b_r] = b4.z;
                Bs[0][b_k + 3][b_r] = b4.w;
            } else {
                *(float4*)&Bs[0][b_k][b_n] = b4;
            }
        }
    }
    __syncthreads();

    for (int kt = 0; kt < KT; kt++) {
        int cur = kt & 1;
        float4 pa, pb;
        bool has_next = (kt + 1 < KT);
        if (has_next) {
            pa = *(const float4*)(Aptr + (kt + 1) * 8);
            if (b_act) {
                if (BT) pb = *(const float4*)(Bptr + (kt + 1) * 8);
                else    pb = *(const float4*)(Bptr + (size_t)(kt + 1) * 8 * ldb);
            }
        }
#pragma unroll
        for (int kk = 0; kk < 8; kk++) {
            float4 a0 = *(const float4*)&As[cur][kk][ty * 8];
            float4 a1 = *(const float4*)&As[cur][kk][ty * 8 + 4];
            float ar[8] = {a0.x, a0.y, a0.z, a0.w, a1.x, a1.y, a1.z, a1.w};
            float br[TN];
#pragma unroll
            for (int j4 = 0; j4 < TN; j4 += 4) {
                float4 bv = *(const float4*)&Bs[cur][kk][tx * TN + j4];
                br[j4 + 0] = bv.x; br[j4 + 1] = bv.y;
                br[j4 + 2] = bv.z; br[j4 + 3] = bv.w;
            }
#pragma unroll
            for (int i = 0; i < 8; i++)
#pragma unroll
                for (int j = 0; j < TN; j++) acc[i][j] += ar[i] * br[j];
        }
        if (has_next) {
            int nxt = cur ^ 1;
            As[nxt][a_k + 0][a_r] = pa.x;
            As[nxt][a_k + 1][a_r] = pa.y;
            As[nxt][a_k + 2][a_r] = pa.z;
            As[nxt][a_k + 3][a_r] = pa.w;
            if (b_act) {
                if (BT) {
                    Bs[nxt][b_k + 0][b_r] = pb.x;
                    Bs[nxt][b_k + 1][b_r] = pb.y;
                    Bs[nxt][b_k + 2][b_r] = pb.z;
                    Bs[nxt][b_k + 3][b_r] = pb.w;
                } else {
                    *(float4*)&Bs[nxt][b_k][b_n] = pb;
                }
            }
            __syncthreads();
        }
    }

#pragma unroll
    for (int i = 0; i < 8; i++) {
        int m = m0 + ty * 8 + i;
#pragma unroll
        for (int j = 0; j < TN; j++) {
            int n = n0 + tx * TN + j;
            float v = acc[i][j];
            if (bias1) v += bias1[n];
            if (bias2) v += bias2[n];
            C[(size_t)m * ldc + n] = v;
        }
    }
}

// ---------------- persistent LSTM kernel ----------------
// 128 blocks x 256 threads. Block bid owns h-cols j = bid*4 .. bid*4+3, i.e.
// 16 gate columns col(c) = (c>>2)*512 + bid*4 + (c&3).  One grid barrier/step.
// W_hh^T columns live in registers (32 floats/thread). h broadcast via global
// double buffer in [k][b] layout. Gate GEMM uses packed f32x2 FMA over batch pairs.
// Shared memory is dynamic (50368 B > 48KB static limit).
__global__ void __launch_bounds__(256) lstm_kernel() {
    extern __shared__ __align__(16) char dynsm[];
    ull*   hs2     = (ull*)dynsm;                              // h[k][b] pairs, 32KB
    float* part_sm = (float*)(dynsm + HS2_BYTES);              // [c][ks*16+b], stride 258
    float (*gsm)[17] = (float(*)[17])(dynsm + HS2_BYTES + PART_BYTES);

    int tid = threadIdx.x;
    int bid = blockIdx.x;

    // phase-1 mapping
    int ks = tid >> 4;       // 0..15 -> k range [ks*32, ks*32+32)
    int c  = tid & 15;       // 0..15 gate-col within block
    int col = (c >> 2) * 512 + bid * 4 + (c & 3);

    // reduce mapping
    int rc = tid >> 4, rb = tid & 15;
    int rcol = (rc >> 2) * 512 + bid * 4 + (rc & 3);

    // update mapping (tid < 64)
    int uj = tid >> 4;       // 0..3 local h col
    int ub = tid & 15;

    // W into registers (one-time)
    float wreg[32];
#pragma unroll
    for (int kk = 0; kk < 32; kk++)
        wreg[kk] = g_WhhT[(size_t)(ks * 32 + kk) * G4H + col];

    // zero h read-buffer for t=0 (buffer 1) ; c-state in regs
    if (tid < 64) g_hbuf[1][bid * 64 + tid] = 0.0f;
    float creg = 0.0f;

    unsigned target = 0;
    if (tid == 0) target = *((volatile unsigned*)&g_bar_phase) + 1;
    grid_bar(target);

    for (int t = 0; t < TT; t++) {
        int rbuf = (t & 1) ^ 1;
        int wbuf = t & 1;

        // broadcast h into smem (32KB, coalesced float4)
        {
            const float4* src = (const float4*)g_hbuf[rbuf];
            float4* dst = (float4*)hs2;
#pragma unroll
            for (int i = 0; i < 8; i++) dst[tid + i * 256] = src[tid + i * 256];
        }
        __syncthreads();

        // partial gate GEMM: this thread: col, k in [ks*32, ks*32+32), all 16 batches
        ull acc[8];
#pragma unroll
        for (int p = 0; p < 8; p++) acc[p] = 0ULL;
#pragma unroll
        for (int kk = 0; kk < 32; kk++) {
            int k = ks * 32 + kk;
            float w = wreg[kk];
            ull w2 = packf2(w, w);
            const ulonglong2* hp = (const ulonglong2*)(hs2 + (size_t)k * 8);
            ulonglong2 h01 = hp[0];
            ulonglong2 h23 = hp[1];
            ulonglong2 h45 = hp[2];
            ulonglong2 h67 = hp[3];
            fma2(acc[0], h01.x, w2);
            fma2(acc[1], h01.y, w2);
            fma2(acc[2], h23.x, w2);
            fma2(acc[3], h23.y, w2);
            fma2(acc[4], h45.x, w2);
            fma2(acc[5], h45.y, w2);
            fma2(acc[6], h67.x, w2);
            fma2(acc[7], h67.y, w2);
        }
        // write partials: part_sm[c*258 + ks*16 + b]
        {
            ull* pp = (ull*)&part_sm[c * 258 + ks * 16];
#pragma unroll
            for (int p = 0; p < 8; p++) pp[p] = acc[p];
        }
        __syncthreads();

        // reduce over ks + add pregates -> gate value for (rc, rb)
        {
            float s = g_pregates[((size_t)(rb * TT + t)) * G4H + rcol];
#pragma unroll
            for (int k2 = 0; k2 < 16; k2++)
                s += part_sm[rc * 258 + k2 * 16 + rb];
            gsm[rc][rb] = s;
        }
        __syncthreads();

        // state update: 64 threads, (j_local, b)
        if (tid < 64) {
            float gi = gsm[0 * 4 + uj][ub];
            float gf = gsm[1 * 4 + uj][ub];
            float gg = gsm[2 * 4 + uj][ub];
            float go = gsm[3 * 4 + uj][ub];
            float ig = sigmoidf_(gi);
            float fg = sigmoidf_(gf);
            float gv = tanhf(gg);
            float og = sigmoidf_(go);
            creg = fg * creg + ig * gv;
            float hn = og * tanhf(creg);
            int j = bid * 4 + uj;
            g_hbuf[wbuf][j * 16 + ub] = hn;
            g_combined[((size_t)(ub * TT + t)) * 768 + j] = hn;
        }

        grid_bar(target);
    }
}

// ---------------- softmax over memory slots (with cosine scaling) --------------
__global__ void __launch_bounds__(256) softmax_kernel() {
    __shared__ float red[256];
    __shared__ float s_kn;
    int p = blockIdx.x;          // 0..32767 (= (b*T+t)*4 + n)
    int tid = threadIdx.x;

    float kv = 0.0f;
    if (tid < DD) {
        float k = g_keys[(size_t)p * DD + tid];
        kv = k * k;
    }
    red[tid] = kv;
    __syncthreads();
    for (int o = 128; o > 0; o >>= 1) {
        if (tid < o) red[tid] += red[tid + o];
        __syncthreads();
    }
    if (tid == 0) s_kn = sqrtf(red[0]);
    __syncthreads();
    float kn = s_kn;
    __syncthreads();

    float v[8];
    float mx = -3.0e38f;
#pragma unroll
    for (int i = 0; i < 8; i++) {
        int m = tid + i * 256;
        float s = g_sims[(size_t)p * MM + m];
        s = s / fmaxf(kn * g_memnorm[m], EPSV);
        v[i] = s;
        mx = fmaxf(mx, s);
    }
    red[tid] = mx;
    __syncthreads();
    for (int o = 128; o > 0; o >>= 1) {
        if (tid < o) red[tid] = fmaxf(red[tid], red[tid + o]);
        __syncthreads();
    }
    mx = red[0];
    __syncthreads();

    float sum = 0.0f;
#pragma unroll
    for (int i = 0; i < 8; i++) {
        v[i] = __expf(v[i] - mx);
        sum += v[i];
    }
    red[tid] = sum;
    __syncthreads();
    for (int o = 128; o > 0; o >>= 1) {
        if (tid < o) red[tid] += red[tid + o];
        __syncthreads();
    }
    float inv = 1.0f / red[0];
#pragma unroll
    for (int i = 0; i < 8; i++) {
        int m = tid + i * 256;
        g_sims[(size_t)p * MM + m] = v[i] * inv;
    }
}

// reads [32768][64] -> combined[r][512 + n*64 + d]
__global__ void copy_reads_kernel() {
    int idx = blockIdx.x * 256 + threadIdx.x;   // 0 .. 32768*64-1
    int p = idx >> 6;
    int d = idx & 63;
    int r = p >> 2;
    int n = p & 3;
    g_combined[(size_t)r * 768 + HH + n * DD + d] = g_reads[idx];
}

// ---------------- launch ----------------
extern "C" void kernel_launch(void* const* d_in, const int* in_sizes, int n_in,
                              void* d_out, int out_size) {
    const float* x      = (const float*)d_in[0];
    const float* memory = (const float*)d_in[1];
    const float* W_ih   = (const float*)d_in[2];
    const float* W_hh   = (const float*)d_in[3];
    const float* b_ih   = (const float*)d_in[4];
    const float* b_hh   = (const float*)d_in[5];
    const float* W_if   = (const float*)d_in[6];
    const float* b_if   = (const float*)d_in[7];
    const float* W_out  = (const float*)d_in[8];
    const float* b_out  = (const float*)d_in[9];
    float* out = (float*)d_out;

    float *pg, *comb, *keys, *sims, *reads;
    cudaGetSymbolAddress((void**)&pg, g_pregates);
    cudaGetSymbolAddress((void**)&comb, g_combined);
    cudaGetSymbolAddress((void**)&keys, g_keys);
    cudaGetSymbolAddress((void**)&sims, g_sims);
    cudaGetSymbolAddress((void**)&reads, g_reads);

    // opt-in to >48KB dynamic smem for the LSTM kernel (attribute call, not an alloc)
    cudaFuncSetAttribute(lstm_kernel, cudaFuncAttributeMaxDynamicSharedMemorySize, LSTM_SMEM);

    // prep
    transpose_whh_kernel<<<(G4H * HH) / 256, 256>>>(W_hh);
    memnorm_kernel<<<MM, 64>>>(memory);

    // pre-gates: [8192,2048] = x[8192,256] @ W_ih^T + (b_ih + b_hh)
    sgemm2<true, 128><<<dim3(G4H / 128, (BB * TT) / 128), 256>>>(
        x, W_ih, pg, BB * TT, G4H, II, II, II, G4H, b_ih, b_hh);

    // sequential LSTM recurrence (persistent, 1 grid barrier/step)
    lstm_kernel<<<NBLK, 256, LSTM_SMEM>>>();

    // keys: [8192,256] = hs(combined[:, :512], lda=768) @ W_if[:256]^T + b_if[:256]
    sgemm2<true, 128><<<dim3(256 / 128, (BB * TT) / 128), 256>>>(
        comb, W_if, keys, BB * TT, NHD * DD, HH, 768, HH, NHD * DD, b_if, nullptr);

    // sims: [32768,2048] = keys[32768,64] @ memory^T
    sgemm2<true, 128><<<dim3(MM / 128, (BB * TT * NHD) / 128), 256>>>(
        keys, memory, sims, BB * TT * NHD, MM, DD, DD, DD, MM, nullptr, nullptr);

    // cosine-scale + softmax (in place on sims)
    softmax_kernel<<<BB * TT * NHD, 256>>>();

    // reads: [32768,64] = attn[32768,2048] @ memory[2048,64]   (NN)
    sgemm2<false, 64><<<dim3(1, (BB * TT * NHD) / 128), 256>>>(
        sims, memory, reads, BB * TT * NHD, DD, MM, MM, DD, DD, nullptr, nullptr);

    copy_reads_kernel<<<(BB * TT * NHD * DD) / 256, 256>>>();

    // out: [8192,256] = combined[8192,768] @ W_out^T + b_out
    sgemm2<true, 128><<<dim3(OO / 128, (BB * TT) / 128), 256>>>(
        comb, W_out, out, BB * TT, OO, HH + NHD * DD, 768, 768, OO, b_out, nullptr);
}

// round 8
// speedup vs baseline: 1.9678x; 1.1823x over previous
#include <cuda_runtime.h>
#include <cuda_bf16.h>
#include <math.h>

// Problem dims
#define BB 16
#define TT 512
#define II 256
#define HH 512
#define MM 2048
#define DD 64
#define NHD 4
#define OO 256
#define G4H 2048  // 4*H
#define EPSV 1e-8f

#define NBLK 128  // persistent LSTM grid (<= SM count -> co-resident)

// LSTM dynamic smem layout
#define HS2_BYTES  (HH * 8 * 8)        // 32768: h[k][b] as ull pairs
#define PART_BYTES (16 * 258 * 4)      // 16512: partials, padded stride
#define GSM_BYTES  (16 * 17 * 4)       // 1088
#define LSTM_SMEM  (HS2_BYTES + PART_BYTES + GSM_BYTES)  // 50368

typedef unsigned long long ull;

// ---------------- scratch (static device globals; no runtime alloc) ------------
__device__ float g_pregates[(size_t)BB * TT * G4H];   // 64 MB, row r = b*T+t
__device__ float g_hbuf[2][HH * BB];                  // [buf][k*16+b], double buffered
__device__ float g_combined[(size_t)BB * TT * (HH + NHD * DD)];  // [8192][768]
__device__ float g_keys[(size_t)BB * TT * NHD * DD];  // [32768][64]
__device__ float g_sims[(size_t)BB * TT * NHD * MM];  // 256 MB, [32768][2048]
__device__ float g_WhhT[HH * G4H];                    // [512][2048]
__device__ float g_memnorm[MM];
__device__ unsigned g_bar_count;
__device__ unsigned g_bar_phase;

// ---------------- helpers ----------------
__device__ __forceinline__ float sigmoidf_(float x) {
    return 1.0f / (1.0f + __expf(-x));
}

__device__ __forceinline__ ull packf2(float a, float b) {
    ull r;
    asm("mov.b64 %0, {%1, %2};" : "=l"(r) : "f"(a), "f"(b));
    return r;
}
__device__ __forceinline__ void fma2(ull& d, ull a, ull b) {
    asm("fma.rn.f32x2 %0, %1, %2, %0;" : "+l"(d) : "l"(a), "l"(b));
}

__device__ __forceinline__ unsigned f2tf(float f) {
    unsigned r;
    asm("cvt.rna.tf32.f32 %0, %1;" : "=r"(r) : "f"(f));
    return r;
}

__device__ __forceinline__ void mma_tf32(float* c, const unsigned* a, const unsigned* b) {
    asm volatile(
        "mma.sync.aligned.m16n8k8.row.col.f32.tf32.tf32.f32 "
        "{%0,%1,%2,%3}, {%4,%5,%6,%7}, {%8,%9}, {%0,%1,%2,%3};"
        : "+f"(c[0]), "+f"(c[1]), "+f"(c[2]), "+f"(c[3])
        : "r"(a[0]), "r"(a[1]), "r"(a[2]), "r"(a[3]), "r"(b[0]), "r"(b[1]));
}

// Self-resetting grid barrier (phase generation counter; safe across graph replays).
__device__ __forceinline__ void grid_bar(unsigned& target) {
    __syncthreads();
    if (threadIdx.x == 0) {
        __threadfence();
        if (atomicAdd(&g_bar_count, 1) == NBLK - 1) {
            g_bar_count = 0;
            __threadfence();
            atomicAdd(&g_bar_phase, 1);
        } else {
            while (*((volatile unsigned*)&g_bar_phase) != target) { __nanosleep(32); }
            __threadfence();
        }
        target += 1;
    }
    __syncthreads();
}

// ---------------- small prep kernels ----------------
__global__ void transpose_whh_kernel(const float* __restrict__ W_hh) {
    int idx = blockIdx.x * 256 + threadIdx.x;  // total 2048*512
    int g = idx & (G4H - 1);
    int k = idx >> 11;
    g_WhhT[k * G4H + g] = W_hh[g * HH + k];
}

__global__ void memnorm_kernel(const float* __restrict__ memory) {
    __shared__ float s[64];
    int m = blockIdx.x;
    float v = memory[m * DD + threadIdx.x];
    s[threadIdx.x] = v * v;
    __syncthreads();
    for (int o = 32; o > 0; o >>= 1) {
        if (threadIdx.x < o) s[threadIdx.x] += s[threadIdx.x + o];
        __syncthreads();
    }
    if (threadIdx.x == 0) g_memnorm[m] = sqrtf(s[0]);
}

// ---------------- tf32 tensor-core GEMM ----------------
// C[m][n] = sum_k A[m*lda+k] * (BT ? B[n*ldb+k] : B[k*ldb+n]) + bias1[n] + bias2[n]
// Block tile 128 x BN, BK=16, double buffered. 8 warps in 4(m) x 2(n); warp tile
// 32 x (BN/2); mma.sync m16n8k8 tf32. M%128==0, N%BN==0, K%16==0, lda/ldb%4==0.
// REMAP: row m writes to C[(m>>2)*768 + 512 + (m&3)*64 + n] (reads->combined fusion).
template <bool BT, int BN, bool REMAP>
__global__ void __launch_bounds__(256) tgemm(
    const float* __restrict__ A, const float* __restrict__ B, float* __restrict__ C,
    int M, int N, int K, int lda, int ldb, int ldc,
    const float* __restrict__ bias1, const float* __restrict__ bias2)
{
    constexpr int WN = BN / 2;    // warp n extent: 64 or 32
    constexpr int NT = WN / 8;    // n-tiles per warp: 8 or 4
    __shared__ unsigned As[2][16][132];
    __shared__ unsigned Bs[2][16][BN + 4];

    int tid = threadIdx.x;
    int wid = tid >> 5, lane = tid & 31;
    int wm = (wid >> 1) * 32;     // 0,32,64,96
    int wn = (wid & 1) * WN;
    int m0 = blockIdx.y * 128;
    int n0 = blockIdx.x * BN;
    int g = lane >> 2, tg = lane & 3;

    float acc[2][NT][4];
#pragma unroll
    for (int i = 0; i < 2; i++)
#pragma unroll
        for (int j = 0; j < NT; j++)
#pragma unroll
            for (int e = 0; e < 4; e++) acc[i][j][e] = 0.0f;

    // A loader: row a_r = tid>>1 (0..127), k offset ak = (tid&1)*8, 2 float4/stage
    int a_r = tid >> 1;
    int ak = (tid & 1) * 8;
    const float* Aptr = A + (size_t)(m0 + a_r) * lda + ak;

    // B loader
    const float* Bptr;
    int bn4 = 0, bk_nn = 0;
    if (BT) {
        // B is [N][K]; rows = n. Same pattern as A. (BN==128 assumed)
        Bptr = B + (size_t)(n0 + a_r) * ldb + ak;
    } else {
        // B is [K][N]; 16 x BN floats/stage; BN==64 -> 1 float4/thread
        bk_nn = tid >> 4;             // 0..15
        bn4 = (tid & 15) * 4;         // 0..60
        Bptr = B + (size_t)bk_nn * ldb + n0 + bn4;
    }

    int KT = K >> 4;

    // prologue: stage 0
    {
        float4 a0 = *(const float4*)Aptr;
        float4 a1 = *(const float4*)(Aptr + 4);
        As[0][ak + 0][a_r] = f2tf(a0.x); As[0][ak + 1][a_r] = f2tf(a0.y);
        As[0][ak + 2][a_r] = f2tf(a0.z); As[0][ak + 3][a_r] = f2tf(a0.w);
        As[0][ak + 4][a_r] = f2tf(a1.x); As[0][ak + 5][a_r] = f2tf(a1.y);
        As[0][ak + 6][a_r] = f2tf(a1.z); As[0][ak + 7][a_r] = f2tf(a1.w);
        if (BT) {
            float4 b0 = *(const float4*)Bptr;
            float4 b1 = *(const float4*)(Bptr + 4);
            Bs[0][ak + 0][a_r] = f2tf(b0.x); Bs[0][ak + 1][a_r] = f2tf(b0.y);
            Bs[0][ak + 2][a_r] = f2tf(b0.z); Bs[0][ak + 3][a_r] = f2tf(b0.w);
            Bs[0][ak + 4][a_r] = f2tf(b1.x); Bs[0][ak + 5][a_r] = f2tf(b1.y);
            Bs[0][ak + 6][a_r] = f2tf(b1.z); Bs[0][ak + 7][a_r] = f2tf(b1.w);
        } else {
            float4 b0 = *(const float4*)Bptr;
            Bs[0][bk_nn][bn4 + 0] = f2tf(b0.x); Bs[0][bk_nn][bn4 + 1] = f2tf(b0.y);
            Bs[0][bk_nn][bn4 + 2] = f2tf(b0.z); Bs[0][bk_nn][bn4 + 3] = f2tf(b0.w);
        }
    }
    __syncthreads();

    for (int kt = 0; kt < KT; kt++) {
        int cur = kt & 1;
        float4 pa0, pa1, pb0, pb1;
        bool has_next = (kt + 1 < KT);
        if (has_next) {
            pa0 = *(const float4*)(Aptr + (kt + 1) * 16);
            pa1 = *(const float4*)(Aptr + (kt + 1) * 16 + 4);
            if (BT) {
                pb0 = *(const float4*)(Bptr + (kt + 1) * 16);
                pb1 = *(const float4*)(Bptr + (kt + 1) * 16 + 4);
            } else {
                pb0 = *(const float4*)(Bptr + (size_t)(kt + 1) * 16 * ldb);
            }
        }

#pragma unroll
        for (int ks = 0; ks < 2; ks++) {
            int kb = ks * 8;
            unsigned af[2][4];
#pragma unroll
            for (int mt = 0; mt < 2; mt++) {
                int row = wm + mt * 16;
                af[mt][0] = As[cur][kb + tg][row + g];
                af[mt][1] = As[cur][kb + tg][row + g + 8];
                af[mt][2] = As[cur][kb + tg + 4][row + g];
                af[mt][3] = As[cur][kb + tg + 4][row + g + 8];
            }
            unsigned bf[NT][2];
#pragma unroll
            for (int nt = 0; nt < NT; nt++) {
                bf[nt][0] = Bs[cur][kb + tg][wn + nt * 8 + g];
                bf[nt][1] = Bs[cur][kb + tg + 4][wn + nt * 8 + g];
            }
#pragma unroll
            for (int mt = 0; mt < 2; mt++)
#pragma unroll
                for (int nt = 0; nt < NT; nt++)
                    mma_tf32(acc[mt][nt], af[mt], bf[nt]);
        }

        if (has_next) {
            int nxt = cur ^ 1;
            As[nxt][ak + 0][a_r] = f2tf(pa0.x); As[nxt][ak + 1][a_r] = f2tf(pa0.y);
            As[nxt][ak + 2][a_r] = f2tf(pa0.z); As[nxt][ak + 3][a_r] = f2tf(pa0.w);
            As[nxt][ak + 4][a_r] = f2tf(pa1.x); As[nxt][ak + 5][a_r] = f2tf(pa1.y);
            As[nxt][ak + 6][a_r] = f2tf(pa1.z); As[nxt][ak + 7][a_r] = f2tf(pa1.w);
            if (BT) {
                Bs[nxt][ak + 0][a_r] = f2tf(pb0.x); Bs[nxt][ak + 1][a_r] = f2tf(pb0.y);
                Bs[nxt][ak + 2][a_r] = f2tf(pb0.z); Bs[nxt][ak + 3][a_r] = f2tf(pb0.w);
                Bs[nxt][ak + 4][a_r] = f2tf(pb1.x); Bs[nxt][ak + 5][a_r] = f2tf(pb1.y);
                Bs[nxt][ak + 6][a_r] = f2tf(pb1.z); Bs[nxt][ak + 7][a_r] = f2tf(pb1.w);
            } else {
                Bs[nxt][bk_nn][bn4 + 0] = f2tf(pb0.x); Bs[nxt][bk_nn][bn4 + 1] = f2tf(pb0.y);
                Bs[nxt][bk_nn][bn4 + 2] = f2tf(pb0.z); Bs[nxt][bk_nn][bn4 + 3] = f2tf(pb0.w);
            }
            __syncthreads();
        }
    }

    // epilogue
#pragma unroll
    for (int mt = 0; mt < 2; mt++) {
        int r0 = m0 + wm + mt * 16 + g;
#pragma unroll
        for (int nt = 0; nt < NT; nt++) {
            int cc = n0 + wn + nt * 8 + tg * 2;
            float bv0 = 0.0f, bv1 = 0.0f;
            if (bias1) { bv0 += bias1[cc]; bv1 += bias1[cc + 1]; }
            if (bias2) { bv0 += bias2[cc]; bv1 += bias2[cc + 1]; }
            float2 v0 = make_float2(acc[mt][nt][0] + bv0, acc[mt][nt][1] + bv1);
            float2 v1 = make_float2(acc[mt][nt][2] + bv0, acc[mt][nt][3] + bv1);
            if (REMAP) {
                int ra = r0, rb2 = r0 + 8;
                size_t o0 = (size_t)(ra >> 2) * 768 + 512 + (ra & 3) * 64 + cc;
                size_t o1 = (size_t)(rb2 >> 2) * 768 + 512 + (rb2 & 3) * 64 + cc;
                *(float2*)&C[o0] = v0;
                *(float2*)&C[o1] = v1;
            } else {
                *(float2*)&C[(size_t)r0 * ldc + cc] = v0;
                *(float2*)&C[(size_t)(r0 + 8) * ldc + cc] = v1;
            }
        }
    }
}

// ---------------- persistent LSTM kernel ----------------
// 128 blocks x 256 threads. Block bid owns h-cols j = bid*4 .. bid*4+3, i.e.
// 16 gate columns col(c) = (c>>2)*512 + bid*4 + (c&3).  One grid barrier/step.
// W_hh^T columns live in registers (32 floats/thread). h broadcast via global
// double buffer in [k][b] layout. Gate GEMM uses packed f32x2 FMA over batch pairs.
__global__ void __launch_bounds__(256) lstm_kernel() {
    extern __shared__ __align__(16) char dynsm[];
    ull*   hs2     = (ull*)dynsm;                              // h[k][b] pairs, 32KB
    float* part_sm = (float*)(dynsm + HS2_BYTES);              // [c][ks*16+b], stride 258
    float (*gsm)[17] = (float(*)[17])(dynsm + HS2_BYTES + PART_BYTES);

    int tid = threadIdx.x;
    int bid = blockIdx.x;

    int ks = tid >> 4;       // 0..15 -> k range [ks*32, ks*32+32)
    int c  = tid & 15;       // 0..15 gate-col within block
    int col = (c >> 2) * 512 + bid * 4 + (c & 3);

    int rc = tid >> 4, rb = tid & 15;
    int rcol = (rc >> 2) * 512 + bid * 4 + (rc & 3);

    int uj = tid >> 4;       // 0..3 local h col (tid<64 path)
    int ub = tid & 15;

    float wreg[32];
#pragma unroll
    for (int kk = 0; kk < 32; kk++)
        wreg[kk] = g_WhhT[(size_t)(ks * 32 + kk) * G4H + col];

    if (tid < 64) g_hbuf[1][bid * 64 + tid] = 0.0f;
    float creg = 0.0f;

    unsigned target = 0;
    if (tid == 0) target = *((volatile unsigned*)&g_bar_phase) + 1;
    grid_bar(target);

    for (int t = 0; t < TT; t++) {
        int rbuf = (t & 1) ^ 1;
        int wbuf = t & 1;

        {
            const float4* src = (const float4*)g_hbuf[rbuf];
            float4* dst = (float4*)hs2;
#pragma unroll
            for (int i = 0; i < 8; i++) dst[tid + i * 256] = src[tid + i * 256];
        }
        __syncthreads();

        ull acc[8];
#pragma unroll
        for (int p = 0; p < 8; p++) acc[p] = 0ULL;
#pragma unroll
        for (int kk = 0; kk < 32; kk++) {
            int k = ks * 32 + kk;
            float w = wreg[kk];
            ull w2 = packf2(w, w);
            const ulonglong2* hp = (const ulonglong2*)(hs2 + (size_t)k * 8);
            ulonglong2 h01 = hp[0];
            ulonglong2 h23 = hp[1];
            ulonglong2 h45 = hp[2];
            ulonglong2 h67 = hp[3];
            fma2(acc[0], h01.x, w2);
            fma2(acc[1], h01.y, w2);
            fma2(acc[2], h23.x, w2);
            fma2(acc[3], h23.y, w2);
            fma2(acc[4], h45.x, w2);
            fma2(acc[5], h45.y, w2);
            fma2(acc[6], h67.x, w2);
            fma2(acc[7], h67.y, w2);
        }
        {
            ull* pp = (ull*)&part_sm[c * 258 + ks * 16];
#pragma unroll
            for (int p = 0; p < 8; p++) pp[p] = acc[p];
        }
        __syncthreads();

        {
            float s = g_pregates[((size_t)(rb * TT + t)) * G4H + rcol];
#pragma unroll
            for (int k2 = 0; k2 < 16; k2++)
                s += part_sm[rc * 258 + k2 * 16 + rb];
            gsm[rc][rb] = s;
        }
        __syncthreads();

        if (tid < 64) {
            float gi = gsm[0 * 4 + uj][ub];
            float gf = gsm[1 * 4 + uj][ub];
            float gg = gsm[2 * 4 + uj][ub];
            float go = gsm[3 * 4 + uj][ub];
            float ig = sigmoidf_(gi);
            float fg = sigmoidf_(gf);
            float gv = tanhf(gg);
            float og = sigmoidf_(go);
            creg = fg * creg + ig * gv;
            float hn = og * tanhf(creg);
            int j = bid * 4 + uj;
            g_hbuf[wbuf][j * 16 + ub] = hn;
            g_combined[((size_t)(ub * TT + t)) * 768 + j] = hn;
        }

        grid_bar(target);
    }
}

// ---------------- softmax over memory slots (with cosine scaling) --------------
__global__ void __launch_bounds__(256) softmax_kernel() {
    __shared__ float red[256];
    __shared__ float s_kn;
    int p = blockIdx.x;          // 0..32767 (= (b*T+t)*4 + n)
    int tid = threadIdx.x;

    float kv = 0.0f;
    if (tid < DD) {
        float k = g_keys[(size_t)p * DD + tid];
        kv = k * k;
    }
    red[tid] = kv;
    __syncthreads();
    for (int o = 128; o > 0; o >>= 1) {
        if (tid < o) red[tid] += red[tid + o];
        __syncthreads();
    }
    if (tid == 0) s_kn = sqrtf(red[0]);
    __syncthreads();
    float kn = s_kn;
    __syncthreads();

    float v[8];
    float mx = -3.0e38f;
#pragma unroll
    for (int i = 0; i < 8; i++) {
        int m = tid + i * 256;
        float s = g_sims[(size_t)p * MM + m];
        s = s / fmaxf(kn * g_memnorm[m], EPSV);
        v[i] = s;
        mx = fmaxf(mx, s);
    }
    red[tid] = mx;
    __syncthreads();
    for (int o = 128; o > 0; o >>= 1) {
        if (tid < o) red[tid] = fmaxf(red[tid], red[tid + o]);
        __syncthreads();
    }
    mx = red[0];
    __syncthreads();

    float sum = 0.0f;
#pragma unroll
    for (int i = 0; i < 8; i++) {
        v[i] = __expf(v[i] - mx);
        sum += v[i];
    }
    red[tid] = sum;
    __syncthreads();
    for (int o = 128; o > 0; o >>= 1) {
        if (tid < o) red[tid] += red[tid + o];
        __syncthreads();
    }
    float inv = 1.0f / red[0];
#pragma unroll
    for (int i = 0; i < 8; i++) {
        int m = tid + i * 256;
        g_sims[(size_t)p * MM + m] = v[i] * inv;
    }
}

// ---------------- launch ----------------
extern "C" void kernel_launch(void* const* d_in, const int* in_sizes, int n_in,
                              void* d_out, int out_size) {
    const float* x      = (const float*)d_in[0];
    const float* memory = (const float*)d_in[1];
    const float* W_ih   = (const float*)d_in[2];
    const float* W_hh   = (const float*)d_in[3];
    const float* b_ih   = (const float*)d_in[4];
    const float* b_hh   = (const float*)d_in[5];
    const float* W_if   = (const float*)d_in[6];
    const float* b_if   = (const float*)d_in[7];
    const float* W_out  = (const float*)d_in[8];
    const float* b_out  = (const float*)d_in[9];
    float* out = (float*)d_out;

    float *pg, *comb, *keys, *sims;
    cudaGetSymbolAddress((void**)&pg, g_pregates);
    cudaGetSymbolAddress((void**)&comb, g_combined);
    cudaGetSymbolAddress((void**)&keys, g_keys);
    cudaGetSymbolAddress((void**)&sims, g_sims);

    // opt-in to >48KB dynamic smem for the LSTM kernel (attribute call, not an alloc)
    cudaFuncSetAttribute(lstm_kernel, cudaFuncAttributeMaxDynamicSharedMemorySize, LSTM_SMEM);

    // prep
    transpose_whh_kernel<<<(G4H * HH) / 256, 256>>>(W_hh);
    memnorm_kernel<<<MM, 64>>>(memory);

    // pre-gates: [8192,2048] = x[8192,256] @ W_ih^T + (b_ih + b_hh)
    tgemm<true, 128, false><<<dim3(G4H / 128, (BB * TT) / 128), 256>>>(
        x, W_ih, pg, BB * TT, G4H, II, II, II, G4H, b_ih, b_hh);

    // sequential LSTM recurrence (persistent, 1 grid barrier/step)
    lstm_kernel<<<NBLK, 256, LSTM_SMEM>>>();

    // keys: [8192,256] = hs(combined[:, :512], lda=768) @ W_if[:256]^T + b_if[:256]
    tgemm<true, 128, false><<<dim3(256 / 128, (BB * TT) / 128), 256>>>(
        comb, W_if, keys, BB * TT, NHD * DD, HH, 768, HH, NHD * DD, b_if, nullptr);

    // sims: [32768,2048] = keys[32768,64] @ memory^T
    tgemm<true, 128, false><<<dim3(MM / 128, (BB * TT * NHD) / 128), 256>>>(
        keys, memory, sims, BB * TT * NHD, MM, DD, DD, DD, MM, nullptr, nullptr);

    // cosine-scale + softmax (in place on sims)
    softmax_kernel<<<BB * TT * NHD, 256>>>();

    // reads: attn[32768,2048] @ memory[2048,64], epilogue writes straight into
    // combined[r][512 + n*64 + d] via REMAP (row m = r*4+n)
    tgemm<false, 64, true><<<dim3(1, (BB * TT * NHD) / 128), 256>>>(
        sims, memory, comb, BB * TT * NHD, DD, MM, MM, DD, 0, nullptr, nullptr);

    // out: [8192,256] = combined[8192,768] @ W_out^T + b_out
    tgemm<true, 128, false><<<dim3(OO / 128, (BB * TT) / 128), 256>>>(
        comb, W_out, out, BB * TT, OO, HH + NHD * DD, 768, 768, OO, b_out, nullptr);
}

// round 9
// speedup vs baseline: 2.1729x; 1.1042x over previous
#include <cuda_runtime.h>
#include <cuda_bf16.h>
#include <math.h>

// Problem dims
#define BB 16
#define TT 512
#define II 256
#define HH 512
#define MM 2048
#define DD 64
#define NHD 4
#define OO 256
#define G4H 2048  // 4*H
#define EPSV 1e-8f

#define NBLK 128  // persistent LSTM grid (<= SM count -> co-resident)

// LSTM dynamic smem layout
#define HS2_BYTES  (HH * 8 * 8)        // 32768: h[k][b] as ull pairs
#define PART_BYTES (16 * 258 * 4)      // 16512: partials, padded stride
#define GSM_BYTES  (16 * 17 * 4)       // 1088
#define LSTM_SMEM  (HS2_BYTES + PART_BYTES + GSM_BYTES)  // 50368

typedef unsigned long long ull;

// ---------------- scratch (static device globals; no runtime alloc) ------------
__device__ float g_pregates[(size_t)BB * TT * G4H];   // 64 MB, row r = b*T+t
__device__ float g_hbuf[2][HH * BB];                  // [buf][k*16+b], double buffered
__device__ float g_combined[(size_t)BB * TT * (HH + NHD * DD)];  // [8192][768]
__device__ float g_keys[(size_t)BB * TT * NHD * DD];  // [32768][64]
__device__ float g_sims[(size_t)BB * TT * NHD * MM];  // 256 MB, [32768][2048]
__device__ float g_WhhT[HH * G4H];                    // [512][2048]
__device__ float g_memnorm[MM];
__device__ volatile unsigned g_arrive[NBLK];          // flag barrier: per-block arrival
__device__ volatile unsigned g_release;               // flag barrier: release epoch

// ---------------- helpers ----------------
__device__ __forceinline__ float sigmoidf_(float x) {
    return 1.0f / (1.0f + __expf(-x));
}

__device__ __forceinline__ ull packf2(float a, float b) {
    ull r;
    asm("mov.b64 %0, {%1, %2};" : "=l"(r) : "f"(a), "f"(b));
    return r;
}
__device__ __forceinline__ void fma2(ull& d, ull a, ull b) {
    asm("fma.rn.f32x2 %0, %1, %2, %0;" : "+l"(d) : "l"(a), "l"(b));
}

__device__ __forceinline__ unsigned f2tf(float f) {
    unsigned r;
    asm("cvt.rna.tf32.f32 %0, %1;" : "=r"(r) : "f"(f));
    return r;
}

__device__ __forceinline__ void mma_tf32(float* c, const unsigned* a, const unsigned* b) {
    asm volatile(
        "mma.sync.aligned.m16n8k8.row.col.f32.tf32.tf32.f32 "
        "{%0,%1,%2,%3}, {%4,%5,%6,%7}, {%8,%9}, {%0,%1,%2,%3};"
        : "+f"(c[0]), "+f"(c[1]), "+f"(c[2]), "+f"(c[3])
        : "r"(a[0]), "r"(a[1]), "r"(a[2]), "r"(a[3]), "r"(b[0]), "r"(b[1]));
}

// Flag-based grid barrier: one volatile store per block into a distinct slot
// (no L2 atomic serialization), block 0 aggregates with 128 parallel pollers,
// publishes g_release. Consumer-side __threadfence() (gpu scope -> CCTL.IVALL)
// invalidates L1 so subsequent g_hbuf reads are coherent. Epochs are absolute
// (seeded from g_release at kernel entry) -> safe across CUDA-graph replays.
__device__ __forceinline__ void grid_bar2(unsigned e, int tid, int bid) {
    __syncthreads();
    if (tid == 0) {
        __threadfence();              // publish this block's global writes
        g_arrive[bid] = e;
    }
    if (bid == 0) {
        if (tid < NBLK) {
            while (g_arrive[tid] != e) { }
        }
        __syncthreads();
        if (tid == 0) g_release = e;
    } else {
        if (tid == 0) {
            while (g_release != e) { }
        }
    }
    if (tid == 0) __threadfence();    // acquire side: flush/invalidate L1
    __syncthreads();
}

// ---------------- small prep kernels ----------------
__global__ void transpose_whh_kernel(const float* __restrict__ W_hh) {
    int idx = blockIdx.x * 256 + threadIdx.x;  // total 2048*512
    int g = idx & (G4H - 1);
    int k = idx >> 11;
    g_WhhT[k * G4H + g] = W_hh[g * HH + k];
}

__global__ void memnorm_kernel(const float* __restrict__ memory) {
    __shared__ float s[64];
    int m = blockIdx.x;
    float v = memory[m * DD + threadIdx.x];
    s[threadIdx.x] = v * v;
    __syncthreads();
    for (int o = 32; o > 0; o >>= 1) {
        if (threadIdx.x < o) s[threadIdx.x] += s[threadIdx.x + o];
        __syncthreads();
    }
    if (threadIdx.x == 0) g_memnorm[m] = sqrtf(s[0]);
}

// ---------------- tf32 tensor-core GEMM ----------------
// C[m][n] = sum_k A[m*lda+k] * (BT ? B[n*ldb+k] : B[k*ldb+n]) + bias1[n] + bias2[n]
// Block tile 128 x BN, BK=16, double buffered. 8 warps in 4(m) x 2(n); warp tile
// 32 x (BN/2); mma.sync m16n8k8 tf32. M%128==0, N%BN==0, K%16==0, lda/ldb%4==0.
// REMAP: row m writes to C[(m>>2)*768 + 512 + (m&3)*64 + n] (reads->combined fusion).
template <bool BT, int BN, bool REMAP>
__global__ void __launch_bounds__(256) tgemm(
    const float* __restrict__ A, const float* __restrict__ B, float* __restrict__ C,
    int M, int N, int K, int lda, int ldb, int ldc,
    const float* __restrict__ bias1, const float* __restrict__ bias2)
{
    constexpr int WN = BN / 2;    // warp n extent: 64 or 32
    constexpr int NT = WN / 8;    // n-tiles per warp: 8 or 4
    __shared__ unsigned As[2][16][132];
    __shared__ unsigned Bs[2][16][BN + 4];

    int tid = threadIdx.x;
    int wid = tid >> 5, lane = tid & 31;
    int wm = (wid >> 1) * 32;     // 0,32,64,96
    int wn = (wid & 1) * WN;
    int m0 = blockIdx.y * 128;
    int n0 = blockIdx.x * BN;
    int g = lane >> 2, tg = lane & 3;

    float acc[2][NT][4];
#pragma unroll
    for (int i = 0; i < 2; i++)
#pragma unroll
        for (int j = 0; j < NT; j++)
#pragma unroll
            for (int e = 0; e < 4; e++) acc[i][j][e] = 0.0f;

    // A loader: row a_r = tid>>1 (0..127), k offset ak = (tid&1)*8, 2 float4/stage
    int a_r = tid >> 1;
    int ak = (tid & 1) * 8;
    const float* Aptr = A + (size_t)(m0 + a_r) * lda + ak;

    // B loader
    const float* Bptr;
    int bn4 = 0, bk_nn = 0;
    if (BT) {
        // B is [N][K]; rows = n. Same pattern as A. (BN==128 assumed)
        Bptr = B + (size_t)(n0 + a_r) * ldb + ak;
    } else {
        // B is [K][N]; 16 x BN floats/stage; BN==64 -> 1 float4/thread
        bk_nn = tid >> 4;             // 0..15
        bn4 = (tid & 15) * 4;         // 0..60
        Bptr = B + (size_t)bk_nn * ldb + n0 + bn4;
    }

    int KT = K >> 4;

    // prologue: stage 0
    {
        float4 a0 = *(const float4*)Aptr;
        float4 a1 = *(const float4*)(Aptr + 4);
        As[0][ak + 0][a_r] = f2tf(a0.x); As[0][ak + 1][a_r] = f2tf(a0.y);
        As[0][ak + 2][a_r] = f2tf(a0.z); As[0][ak + 3][a_r] = f2tf(a0.w);
        As[0][ak + 4][a_r] = f2tf(a1.x); As[0][ak + 5][a_r] = f2tf(a1.y);
        As[0][ak + 6][a_r] = f2tf(a1.z); As[0][ak + 7][a_r] = f2tf(a1.w);
        if (BT) {
            float4 b0 = *(const float4*)Bptr;
            float4 b1 = *(const float4*)(Bptr + 4);
            Bs[0][ak + 0][a_r] = f2tf(b0.x); Bs[0][ak + 1][a_r] = f2tf(b0.y);
            Bs[0][ak + 2][a_r] = f2tf(b0.z); Bs[0][ak + 3][a_r] = f2tf(b0.w);
            Bs[0][ak + 4][a_r] = f2tf(b1.x); Bs[0][ak + 5][a_r] = f2tf(b1.y);
            Bs[0][ak + 6][a_r] = f2tf(b1.z); Bs[0][ak + 7][a_r] = f2tf(b1.w);
        } else {
            float4 b0 = *(const float4*)Bptr;
            Bs[0][bk_nn][bn4 + 0] = f2tf(b0.x); Bs[0][bk_nn][bn4 + 1] = f2tf(b0.y);
            Bs[0][bk_nn][bn4 + 2] = f2tf(b0.z); Bs[0][bk_nn][bn4 + 3] = f2tf(b0.w);
        }
    }
    __syncthreads();

    for (int kt = 0; kt < KT; kt++) {
        int cur = kt & 1;
        float4 pa0, pa1, pb0, pb1;
        bool has_next = (kt + 1 < KT);
        if (has_next) {
            pa0 = *(const float4*)(Aptr + (kt + 1) * 16);
            pa1 = *(const float4*)(Aptr + (kt + 1) * 16 + 4);
            if (BT) {
                pb0 = *(const float4*)(Bptr + (kt + 1) * 16);
                pb1 = *(const float4*)(Bptr + (kt + 1) * 16 + 4);
            } else {
                pb0 = *(const float4*)(Bptr + (size_t)(kt + 1) * 16 * ldb);
            }
        }

#pragma unroll
        for (int ks = 0; ks < 2; ks++) {
            int kb = ks * 8;
            unsigned af[2][4];
#pragma unroll
            for (int mt = 0; mt < 2; mt++) {
                int row = wm + mt * 16;
                af[mt][0] = As[cur][kb + tg][row + g];
                af[mt][1] = As[cur][kb + tg][row + g + 8];
                af[mt][2] = As[cur][kb + tg + 4][row + g];
                af[mt][3] = As[cur][kb + tg + 4][row + g + 8];
            }
            unsigned bf[NT][2];
#pragma unroll
            for (int nt = 0; nt < NT; nt++) {
                bf[nt][0] = Bs[cur][kb + tg][wn + nt * 8 + g];
                bf[nt][1] = Bs[cur][kb + tg + 4][wn + nt * 8 + g];
            }
#pragma unroll
            for (int mt = 0; mt < 2; mt++)
#pragma unroll
                for (int nt = 0; nt < NT; nt++)
                    mma_tf32(acc[mt][nt], af[mt], bf[nt]);
        }

        if (has_next) {
            int nxt = cur ^ 1;
            As[nxt][ak + 0][a_r] = f2tf(pa0.x); As[nxt][ak + 1][a_r] = f2tf(pa0.y);
            As[nxt][ak + 2][a_r] = f2tf(pa0.z); As[nxt][ak + 3][a_r] = f2tf(pa0.w);
            As[nxt][ak + 4][a_r] = f2tf(pa1.x); As[nxt][ak + 5][a_r] = f2tf(pa1.y);
            As[nxt][ak + 6][a_r] = f2tf(pa1.z); As[nxt][ak + 7][a_r] = f2tf(pa1.w);
            if (BT) {
                Bs[nxt][ak + 0][a_r] = f2tf(pb0.x); Bs[nxt][ak + 1][a_r] = f2tf(pb0.y);
                Bs[nxt][ak + 2][a_r] = f2tf(pb0.z); Bs[nxt][ak + 3][a_r] = f2tf(pb0.w);
                Bs[nxt][ak + 4][a_r] = f2tf(pb1.x); Bs[nxt][ak + 5][a_r] = f2tf(pb1.y);
                Bs[nxt][ak + 6][a_r] = f2tf(pb1.z); Bs[nxt][ak + 7][a_r] = f2tf(pb1.w);
            } else {
                Bs[nxt][bk_nn][bn4 + 0] = f2tf(pb0.x); Bs[nxt][bk_nn][bn4 + 1] = f2tf(pb0.y);
                Bs[nxt][bk_nn][bn4 + 2] = f2tf(pb0.z); Bs[nxt][bk_nn][bn4 + 3] = f2tf(pb0.w);
            }
            __syncthreads();
        }
    }

    // epilogue
#pragma unroll
    for (int mt = 0; mt < 2; mt++) {
        int r0 = m0 + wm + mt * 16 + g;
#pragma unroll
        for (int nt = 0; nt < NT; nt++) {
            int cc = n0 + wn + nt * 8 + tg * 2;
            float bv0 = 0.0f, bv1 = 0.0f;
            if (bias1) { bv0 += bias1[cc]; bv1 += bias1[cc + 1]; }
            if (bias2) { bv0 += bias2[cc]; bv1 += bias2[cc + 1]; }
            float2 v0 = make_float2(acc[mt][nt][0] + bv0, acc[mt][nt][1] + bv1);
            float2 v1 = make_float2(acc[mt][nt][2] + bv0, acc[mt][nt][3] + bv1);
            if (REMAP) {
                int ra = r0, rb2 = r0 + 8;
                size_t o0 = (size_t)(ra >> 2) * 768 + 512 + (ra & 3) * 64 + cc;
                size_t o1 = (size_t)(rb2 >> 2) * 768 + 512 + (rb2 & 3) * 64 + cc;
                *(float2*)&C[o0] = v0;
                *(float2*)&C[o1] = v1;
            } else {
                *(float2*)&C[(size_t)r0 * ldc + cc] = v0;
                *(float2*)&C[(size_t)(r0 + 8) * ldc + cc] = v1;
            }
        }
    }
}

// ---------------- persistent LSTM kernel ----------------
// 128 blocks x 256 threads. Block bid owns h-cols j = bid*4 .. bid*4+3, i.e.
// 16 gate columns col(c) = (c>>2)*512 + bid*4 + (c&3).  One grid barrier/step
// (flag barrier). W_hh^T in registers (32 floats/thread). h via global double
// buffer in [k][b] layout. Gate GEMM uses packed f32x2 FMA over batch pairs.
// g_pregates for step t prefetched at loop top (off the critical path).
__global__ void __launch_bounds__(256) lstm_kernel() {
    extern __shared__ __align__(16) char dynsm[];
    ull*   hs2     = (ull*)dynsm;                              // h[k][b] pairs, 32KB
    float* part_sm = (float*)(dynsm + HS2_BYTES);              // [c][ks*16+b], stride 258
    float (*gsm)[17] = (float(*)[17])(dynsm + HS2_BYTES + PART_BYTES);

    int tid = threadIdx.x;
    int bid = blockIdx.x;

    int ks = tid >> 4;       // 0..15 -> k range [ks*32, ks*32+32)
    int c  = tid & 15;       // 0..15 gate-col within block
    int col = (c >> 2) * 512 + bid * 4 + (c & 3);

    int rc = tid >> 4, rb = tid & 15;
    int rcol = (rc >> 2) * 512 + bid * 4 + (rc & 3);

    int uj = tid >> 4;       // 0..3 local h col (tid<64 path)
    int ub = tid & 15;

    float wreg[32];
#pragma unroll
    for (int kk = 0; kk < 32; kk++)
        wreg[kk] = g_WhhT[(size_t)(ks * 32 + kk) * G4H + col];

    if (tid < 64) g_hbuf[1][bid * 64 + tid] = 0.0f;
    float creg = 0.0f;

    unsigned e = g_release + 1;   // stable: release only advances after ALL arrive
    grid_bar2(e, tid, bid);
    e++;

    for (int t = 0; t < TT; t++) {
        int rbuf = (t & 1) ^ 1;
        int wbuf = t & 1;

        // prefetch this step's pregate (independent of h -> hides L2/DRAM latency)
        float pre = g_pregates[((size_t)(rb * TT + t)) * G4H + rcol];

        // broadcast h into smem (32KB, coalesced float4)
        {
            const float4* src = (const float4*)g_hbuf[rbuf];
            float4* dst = (float4*)hs2;
#pragma unroll
            for (int i = 0; i < 8; i++) dst[tid + i * 256] = src[tid + i * 256];
        }
        __syncthreads();

        ull acc[8];
#pragma unroll
        for (int p = 0; p < 8; p++) acc[p] = 0ULL;
#pragma unroll
        for (int kk = 0; kk < 32; kk++) {
            int k = ks * 32 + kk;
            float w = wreg[kk];
            ull w2 = packf2(w, w);
            const ulonglong2* hp = (const ulonglong2*)(hs2 + (size_t)k * 8);
            ulonglong2 h01 = hp[0];
            ulonglong2 h23 = hp[1];
            ulonglong2 h45 = hp[2];
            ulonglong2 h67 = hp[3];
            fma2(acc[0], h01.x, w2);
            fma2(acc[1], h01.y, w2);
            fma2(acc[2], h23.x, w2);
            fma2(acc[3], h23.y, w2);
            fma2(acc[4], h45.x, w2);
            fma2(acc[5], h45.y, w2);
            fma2(acc[6], h67.x, w2);
            fma2(acc[7], h67.y, w2);
        }
        {
            ull* pp = (ull*)&part_sm[c * 258 + ks * 16];
#pragma unroll
            for (int p = 0; p < 8; p++) pp[p] = acc[p];
        }
        __syncthreads();

        {
            float s = pre;
#pragma unroll
            for (int k2 = 0; k2 < 16; k2++)
                s += part_sm[rc * 258 + k2 * 16 + rb];
            gsm[rc][rb] = s;
        }
        __syncthreads();

        if (tid < 64) {
            float gi = gsm[0 * 4 + uj][ub];
            float gf = gsm[1 * 4 + uj][ub];
            float gg = gsm[2 * 4 + uj][ub];
            float go = gsm[3 * 4 + uj][ub];
            float ig = sigmoidf_(gi);
            float fg = sigmoidf_(gf);
            float gv = tanhf(gg);
            float og = sigmoidf_(go);
            creg = fg * creg + ig * gv;
            float hn = og * tanhf(creg);
            int j = bid * 4 + uj;
            g_hbuf[wbuf][j * 16 + ub] = hn;
            g_combined[((size_t)(ub * TT + t)) * 768 + j] = hn;
        }

        grid_bar2(e, tid, bid);
        e++;
    }
}

// ---------------- softmax over memory slots (with cosine scaling) --------------
__global__ void __launch_bounds__(256) softmax_kernel() {
    __shared__ float red[256];
    __shared__ float s_kn;
    int p = blockIdx.x;          // 0..32767 (= (b*T+t)*4 + n)
    int tid = threadIdx.x;

    float kv = 0.0f;
    if (tid < DD) {
        float k = g_keys[(size_t)p * DD + tid];
        kv = k * k;
    }
    red[tid] = kv;
    __syncthreads();
    for (int o = 128; o > 0; o >>= 1) {
        if (tid < o) red[tid] += red[tid + o];
        __syncthreads();
    }
    if (tid == 0) s_kn = sqrtf(red[0]);
    __syncthreads();
    float kn = s_kn;
    __syncthreads();

    float v[8];
    float mx = -3.0e38f;
#pragma unroll
    for (int i = 0; i < 8; i++) {
        int m = tid + i * 256;
        float s = g_sims[(size_t)p * MM + m];
        s = s / fmaxf(kn * g_memnorm[m], EPSV);
        v[i] = s;
        mx = fmaxf(mx, s);
    }
    red[tid] = mx;
    __syncthreads();
    for (int o = 128; o > 0; o >>= 1) {
        if (tid < o) red[tid] = fmaxf(red[tid], red[tid + o]);
        __syncthreads();
    }
    mx = red[0];
    __syncthreads();

    float sum = 0.0f;
#pragma unroll
    for (int i = 0; i < 8; i++) {
        v[i] = __expf(v[i] - mx);
        sum += v[i];
    }
    red[tid] = sum;
    __syncthreads();
    for (int o = 128; o > 0; o >>= 1) {
        if (tid < o) red[tid] += red[tid + o];
        __syncthreads();
    }
    float inv = 1.0f / red[0];
#pragma unroll
    for (int i = 0; i < 8; i++) {
        int m = tid + i * 256;
        g_sims[(size_t)p * MM + m] = v[i] * inv;
    }
}

// ---------------- launch ----------------
extern "C" void kernel_launch(void* const* d_in, const int* in_sizes, int n_in,
                              void* d_out, int out_size) {
    const float* x      = (const float*)d_in[0];
    const float* memory = (const float*)d_in[1];
    const float* W_ih   = (const float*)d_in[2];
    const float* W_hh   = (const float*)d_in[3];
    const float* b_ih   = (const float*)d_in[4];
    const float* b_hh   = (const float*)d_in[5];
    const float* W_if   = (const float*)d_in[6];
    const float* b_if   = (const float*)d_in[7];
    const float* W_out  = (const float*)d_in[8];
    const float* b_out  = (const float*)d_in[9];
    float* out = (float*)d_out;

    float *pg, *comb, *keys, *sims;
    cudaGetSymbolAddress((void**)&pg, g_pregates);
    cudaGetSymbolAddress((void**)&comb, g_combined);
    cudaGetSymbolAddress((void**)&keys, g_keys);
    cudaGetSymbolAddress((void**)&sims, g_sims);

    // opt-in to >48KB dynamic smem for the LSTM kernel (attribute call, not an alloc)
    cudaFuncSetAttribute(lstm_kernel, cudaFuncAttributeMaxDynamicSharedMemorySize, LSTM_SMEM);

    // prep
    transpose_whh_kernel<<<(G4H * HH) / 256, 256>>>(W_hh);
    memnorm_kernel<<<MM, 64>>>(memory);

    // pre-gates: [8192,2048] = x[8192,256] @ W_ih^T + (b_ih + b_hh)
    tgemm<true, 128, false><<<dim3(G4H / 128, (BB * TT) / 128), 256>>>(
        x, W_ih, pg, BB * TT, G4H, II, II, II, G4H, b_ih, b_hh);

    // sequential LSTM recurrence (persistent, 1 flag-barrier/step)
    lstm_kernel<<<NBLK, 256, LSTM_SMEM>>>();

    // keys: [8192,256] = hs(combined[:, :512], lda=768) @ W_if[:256]^T + b_if[:256]
    tgemm<true, 128, false><<<dim3(256 / 128, (BB * TT) / 128), 256>>>(
        comb, W_if, keys, BB * TT, NHD * DD, HH, 768, HH, NHD * DD, b_if, nullptr);

    // sims: [32768,2048] = keys[32768,64] @ memory^T
    tgemm<true, 128, false><<<dim3(MM / 128, (BB * TT * NHD) / 128), 256>>>(
        keys, memory, sims, BB * TT * NHD, MM, DD, DD, DD, MM, nullptr, nullptr);

    // cosine-scale + softmax (in place on sims)
    softmax_kernel<<<BB * TT * NHD, 256>>>();

    // reads: attn[32768,2048] @ memory[2048,64], epilogue writes straight into
    // combined[r][512 + n*64 + d] via REMAP (row m = r*4+n)
    tgemm<false, 64, true><<<dim3(1, (BB * TT * NHD) / 128), 256>>>(
        sims, memory, comb, BB * TT * NHD, DD, MM, MM, DD, 0, nullptr, nullptr);

    // out: [8192,256] = combined[8192,768] @ W_out^T + b_out
    tgemm<true, 128, false><<<dim3(OO / 128, (BB * TT) / 128), 256>>>(
        comb, W_out, out, BB * TT, OO, HH + NHD * DD, 768, 768, OO, b_out, nullptr);
}